// round 4
// baseline (speedup 1.0000x reference)
#include <cuda_runtime.h>
#include <cstdint>
#include <cstddef>

// ============================================================================
// RhythmMemoryUpdater — GB300 sm_103a (base sm_103 target: mma.sync tf32 path)
//   L = 1  =>  out = node_memories; out[node_ids] = LN( x @ W'^T + lin_b )
//   x = [messages | node_memories[node_ids]] (K=256)
//   W'[d,c] = lin_w[d,c] * conv_w[c, period/2]
//
// k_clear/k_mark: byte mask of updated node rows
// rhythm_fused:   persistent kernel; per iteration: copy 256 non-updated rows
//                 (mask-skip) + one 64-row GEMM tile (W' static in registers,
//                 x via 3-stage cp.async pipeline) + LayerNorm + scatter
// ============================================================================

#define NDIM 128
#define KDIM 256
#define TILE_M 64
#define NTHREADS 256
#define NCTAS 148
#define STAGES 3
#define SX_STRIDE 260            // floats per staged row (1040B)
#define CHUNK_ROWS 256
#define CHUNK_F4 (CHUNK_ROWS * 32)

__device__ uint8_t g_mask[1 << 20];   // covers up to 1,048,576 node rows

// ---------------- helpers ----------------
__device__ __forceinline__ uint32_t smem_u32(const void* p) {
    uint32_t a;
    asm("{ .reg .u64 t; cvta.to.shared.u64 t, %1; cvt.u32.u64 %0, t; }" : "=r"(a) : "l"(p));
    return a;
}
__device__ __forceinline__ uint32_t f2tf32(float f) {
    uint32_t o;
    asm("cvt.rna.tf32.f32 %0, %1;" : "=r"(o) : "f"(f));
    return o;
}
__device__ __forceinline__ void mma_tf32(float c[4], uint32_t a0, uint32_t a1,
                                         uint32_t a2, uint32_t a3,
                                         uint32_t b0, uint32_t b1) {
    asm volatile(
        "mma.sync.aligned.m16n8k8.row.col.f32.tf32.tf32.f32 "
        "{%0,%1,%2,%3}, {%4,%5,%6,%7}, {%8,%9}, {%0,%1,%2,%3};"
        : "+f"(c[0]), "+f"(c[1]), "+f"(c[2]), "+f"(c[3])
        : "r"(a0), "r"(a1), "r"(a2), "r"(a3), "r"(b0), "r"(b1));
}
__device__ __forceinline__ void cp_async16(uint32_t dst, const void* src) {
    asm volatile("cp.async.cg.shared.global [%0], [%1], 16;" :: "r"(dst), "l"(src));
}
#define CP_COMMIT() asm volatile("cp.async.commit_group;" ::: "memory")
#define CP_WAIT1()  asm volatile("cp.async.wait_group 1;" ::: "memory")
#define CP_WAIT0()  asm volatile("cp.async.wait_group 0;" ::: "memory")

// ============================================================================
// mask kernels
// ============================================================================
__global__ void __launch_bounds__(256) k_clear(int nbytes16) {
    uint4 z = make_uint4(0, 0, 0, 0);
    uint4* m = (uint4*)g_mask;
    for (int i = blockIdx.x * 256 + threadIdx.x; i < nbytes16; i += gridDim.x * 256)
        m[i] = z;
}
__global__ void __launch_bounds__(256) k_mark(const int* __restrict__ ids, int n) {
    int i = blockIdx.x * 256 + threadIdx.x;
    if (i < n) g_mask[ids[i]] = 1;
}

// ============================================================================
// fused persistent kernel
// ============================================================================
__global__ void __launch_bounds__(NTHREADS, 1) rhythm_fused(
    const int*   __restrict__ node_ids,
    const float* __restrict__ messages,
    const float* __restrict__ node_mem,
    const float* __restrict__ conv_w,
    const float* __restrict__ lin_w,
    const float* __restrict__ lin_b,
    const float* __restrict__ ln_g,
    const float* __restrict__ ln_bt,
    float*       __restrict__ out,
    int ntiles, int nchunks, int nrows, int period, int pad)
{
    extern __shared__ float sX[];                 // [STAGES][TILE_M * SX_STRIDE]
    __shared__ int    s_node[STAGES][TILE_M];
    __shared__ float2 s_part[8][TILE_M];
    __shared__ float2 s_stats[TILE_M];

    const int tid  = threadIdx.x;
    const int lane = tid & 31;
    const int wid  = tid >> 5;

    // ---- static per-warp W' fragments (A operand of C^T = W' * x^T) ----
    const int d1 = wid * 16 + (lane >> 2);
    const int d2 = d1 + 8;
    const int kbase = lane & 3;

    uint32_t areg[32][4];
#pragma unroll
    for (int kt = 0; kt < 32; kt++) {
        int k1 = kt * 8 + kbase, k2 = k1 + 4;
        float w1 = __ldg(conv_w + k1 * period + pad);
        float w2 = __ldg(conv_w + k2 * period + pad);
        areg[kt][0] = f2tf32(__ldg(lin_w + d1 * KDIM + k1) * w1);
        areg[kt][1] = f2tf32(__ldg(lin_w + d2 * KDIM + k1) * w1);
        areg[kt][2] = f2tf32(__ldg(lin_w + d1 * KDIM + k2) * w2);
        areg[kt][3] = f2tf32(__ldg(lin_w + d2 * KDIM + k2) * w2);
    }
    const float bia1 = __ldg(lin_b + d1), bia2 = __ldg(lin_b + d2);
    const float gm1  = __ldg(ln_g + d1),  gm2  = __ldg(ln_g + d2);
    const float bt1  = __ldg(ln_bt + d1), bt2  = __ldg(ln_bt + d2);

    // ---- cp.async stage: 64 rows x 256 floats (64 float4 chunks/row) ----
    auto stage_tile = [&](int tile, int slot) {
        if (tile >= ntiles) return;
        float* dstS = sX + (size_t)slot * TILE_M * SX_STRIDE;
#pragma unroll
        for (int i = 0; i < 16; i++) {
            int idx = i * NTHREADS + tid;     // 4096 chunks of 16B
            int row = idx >> 6, c = idx & 63;
            long long gr = (long long)tile * TILE_M + row;
            const float4* src;
            if (c < 32) {
                src = (const float4*)messages + gr * 32 + c;
            } else {
                int nd = __ldg(node_ids + gr);
                if (c == 32) s_node[slot][row] = nd;
                src = (const float4*)node_mem + (long long)nd * 32 + (c - 32);
            }
            cp_async16(smem_u32(dstS + row * SX_STRIDE + c * 4), src);
        }
    };

    // ---- prologue: prefetch two tiles ----
    stage_tile(blockIdx.x, 0);
    CP_COMMIT();
    stage_tile(blockIdx.x + gridDim.x, 1);
    CP_COMMIT();

    const float4* src4 = (const float4*)node_mem;
    float4*       dst4 = (float4*)out;

    for (int it = 0;; it++) {
        int tile  = blockIdx.x + it * gridDim.x;
        int chunk = blockIdx.x + it * gridDim.x;
        bool hasT = tile < ntiles, hasC = chunk < nchunks;
        if (!hasT && !hasC) break;

        // ======== copy part (mask-skip), overlaps pending cp.async ========
        if (hasC) {
            int base = chunk * CHUNK_F4;
#pragma unroll 4
            for (int j = 0; j < 32; j++) {
                int idx = base + j * NTHREADS + tid;   // warp-uniform row
                int row = idx >> 5;
                if (row < nrows && g_mask[row] == 0) dst4[idx] = src4[idx];
            }
        }

        // ======== GEMM tile ========
        if (hasT) {
            CP_WAIT1();
            __syncthreads();
            const int slot = it % STAGES;
            const float* X = sX + (size_t)slot * TILE_M * SX_STRIDE;

            float cacc[8][4];
#pragma unroll
            for (int nt = 0; nt < 8; nt++)
#pragma unroll
                for (int j = 0; j < 4; j++) cacc[nt][j] = 0.f;

            const float* xb = X + (lane >> 2) * SX_STRIDE + kbase;
#pragma unroll
            for (int kt = 0; kt < 32; kt++) {
#pragma unroll
                for (int nt = 0; nt < 8; nt++) {
                    const float* xp = xb + nt * 8 * SX_STRIDE + kt * 8;
                    uint32_t b0 = f2tf32(xp[0]);
                    uint32_t b1 = f2tf32(xp[4]);
                    mma_tf32(cacc[nt], areg[kt][0], areg[kt][1],
                             areg[kt][2], areg[kt][3], b0, b1);
                }
            }

            // ---- bias + per-row partial stats (sum over this warp's 16 d) ----
#pragma unroll
            for (int nt = 0; nt < 8; nt++) {
                float vA0 = cacc[nt][0] + bia1;   // (d1, brA)
                float vA1 = cacc[nt][1] + bia1;   // (d1, brA+1)
                float vB0 = cacc[nt][2] + bia2;   // (d2, brA)
                float vB1 = cacc[nt][3] + bia2;   // (d2, brA+1)
                cacc[nt][0] = vA0; cacc[nt][1] = vA1;
                cacc[nt][2] = vB0; cacc[nt][3] = vB1;
                float s0 = vA0 + vB0, q0 = vA0 * vA0 + vB0 * vB0;
                float s1 = vA1 + vB1, q1 = vA1 * vA1 + vB1 * vB1;
#pragma unroll
                for (int m = 4; m <= 16; m <<= 1) {
                    s0 += __shfl_xor_sync(0xffffffffu, s0, m);
                    q0 += __shfl_xor_sync(0xffffffffu, q0, m);
                    s1 += __shfl_xor_sync(0xffffffffu, s1, m);
                    q1 += __shfl_xor_sync(0xffffffffu, q1, m);
                }
                if (lane < 4) {
                    int brA = nt * 8 + lane * 2;
                    s_part[wid][brA]     = make_float2(s0, q0);
                    s_part[wid][brA + 1] = make_float2(s1, q1);
                }
            }
            __syncthreads();

            if (tid < TILE_M) {
                float s = 0.f, q = 0.f;
#pragma unroll
                for (int w = 0; w < 8; w++) {
                    float2 p = s_part[w][tid];
                    s += p.x; q += p.y;
                }
                float mean = s * (1.0f / 128.0f);
                float var  = q * (1.0f / 128.0f) - mean * mean;
                s_stats[tid] = make_float2(mean, rsqrtf(var + 1e-5f));
            }
            __syncthreads();

            // ---- normalize + scatter store ----
#pragma unroll
            for (int nt = 0; nt < 8; nt++) {
                int brA = nt * 8 + (lane & 3) * 2;
                float2 stA = s_stats[brA], stB = s_stats[brA + 1];
                long long ndA = s_node[slot][brA];
                long long ndB = s_node[slot][brA + 1];
                out[ndA * NDIM + d1] = (cacc[nt][0] - stA.x) * stA.y * gm1 + bt1;
                out[ndB * NDIM + d1] = (cacc[nt][1] - stB.x) * stB.y * gm1 + bt1;
                out[ndA * NDIM + d2] = (cacc[nt][2] - stA.x) * stA.y * gm2 + bt2;
                out[ndB * NDIM + d2] = (cacc[nt][3] - stB.x) * stB.y * gm2 + bt2;
            }

            // ---- prefetch tile two iterations ahead into recycled slot ----
            stage_tile(tile + 2 * gridDim.x, (it + 2) % STAGES);
            CP_COMMIT();
        }
    }
    CP_WAIT0();
}

// ============================================================================
// launch
// ============================================================================
extern "C" void kernel_launch(void* const* d_in, const int* in_sizes, int n_in,
                              void* d_out, int out_size) {
    const int*   node_ids = (const int*)  d_in[0];
    const float* messages = (const float*)d_in[1];
    const float* node_mem = (const float*)d_in[2];
    const float* conv_w   = (const float*)d_in[3];
    const float* lin_w    = (const float*)d_in[4];
    const float* lin_b    = (const float*)d_in[5];
    const float* ln_g     = (const float*)d_in[6];
    const float* ln_bt    = (const float*)d_in[7];
    float* out = (float*)d_out;

    int Btot    = in_sizes[1] / NDIM;            // 262144
    int ntiles  = Btot / TILE_M;                 // 4096
    int period  = in_sizes[3] / KDIM;            // 7
    int pad     = period / 2;                    // 3 (L == 1 path)
    int nrows   = out_size / NDIM;               // 1,000,000
    int nchunks = (nrows + CHUNK_ROWS - 1) / CHUNK_ROWS;

    // mask of rows updated by the scatter
    k_clear<<<64, 256>>>((1 << 20) / 16);
    k_mark<<<(Btot + 255) / 256, 256>>>(node_ids, Btot);

    const int dyn_smem = STAGES * TILE_M * SX_STRIDE * 4;   // ~200 KB
    static int configured = -1;
    if (configured != dyn_smem) {
        cudaFuncSetAttribute(rhythm_fused, cudaFuncAttributeMaxDynamicSharedMemorySize,
                             dyn_smem);
        configured = dyn_smem;
    }
    rhythm_fused<<<NCTAS, NTHREADS, dyn_smem>>>(node_ids, messages, node_mem, conv_w,
                                                lin_w, lin_b, ln_g, ln_bt, out,
                                                ntiles, nchunks, nrows, period, pad);
}

// round 5
// speedup vs baseline: 1.6394x; 1.6394x over previous
#include <cuda_runtime.h>
#include <cstdint>
#include <cstddef>

// ============================================================================
// RhythmMemoryUpdater — GB300 sm_103a (base sm_103 target: mma.sync tf32 path)
//   L = 1  =>  out = node_memories; out[node_ids] = LN( x @ W'^T + lin_b )
//   x = [messages | node_memories[node_ids]] (K=256)
//   W'[d,c] = lin_w[d,c] * conv_w[c, period/2]
//
// k_clear/k_mark: byte mask of updated node rows
// k_copy_masked:  high-occupancy copy of non-updated rows (2048 CTAs)
// rhythm_gemm:    persistent 148-CTA GEMM (W' in regs, 3-stage cp.async x
//                 pipeline) + bias + LayerNorm + scatter
// ============================================================================

#define NDIM 128
#define KDIM 256
#define TILE_M 64
#define NTHREADS 256
#define NCTAS 148
#define STAGES 3
#define SX_STRIDE 260            // floats per staged row (1040B)

__device__ uint8_t g_mask[1 << 20];   // covers up to 1,048,576 node rows

// ---------------- helpers ----------------
__device__ __forceinline__ uint32_t smem_u32(const void* p) {
    uint32_t a;
    asm("{ .reg .u64 t; cvta.to.shared.u64 t, %1; cvt.u32.u64 %0, t; }" : "=r"(a) : "l"(p));
    return a;
}
__device__ __forceinline__ uint32_t f2tf32(float f) {
    uint32_t o;
    asm("cvt.rna.tf32.f32 %0, %1;" : "=r"(o) : "f"(f));
    return o;
}
__device__ __forceinline__ void mma_tf32(float c[4], uint32_t a0, uint32_t a1,
                                         uint32_t a2, uint32_t a3,
                                         uint32_t b0, uint32_t b1) {
    asm volatile(
        "mma.sync.aligned.m16n8k8.row.col.f32.tf32.tf32.f32 "
        "{%0,%1,%2,%3}, {%4,%5,%6,%7}, {%8,%9}, {%0,%1,%2,%3};"
        : "+f"(c[0]), "+f"(c[1]), "+f"(c[2]), "+f"(c[3])
        : "r"(a0), "r"(a1), "r"(a2), "r"(a3), "r"(b0), "r"(b1));
}
__device__ __forceinline__ void cp_async16(uint32_t dst, const void* src) {
    asm volatile("cp.async.cg.shared.global [%0], [%1], 16;" :: "r"(dst), "l"(src));
}
#define CP_COMMIT() asm volatile("cp.async.commit_group;" ::: "memory")
#define CP_WAIT1()  asm volatile("cp.async.wait_group 1;" ::: "memory")
#define CP_WAIT0()  asm volatile("cp.async.wait_group 0;" ::: "memory")

// ============================================================================
// mask kernels
// ============================================================================
__global__ void __launch_bounds__(256) k_clear(int nbytes16) {
    uint4 z = make_uint4(0, 0, 0, 0);
    uint4* m = (uint4*)g_mask;
    for (int i = blockIdx.x * 256 + threadIdx.x; i < nbytes16; i += gridDim.x * 256)
        m[i] = z;
}
__global__ void __launch_bounds__(256) k_mark(const int* __restrict__ ids, int n) {
    int i = blockIdx.x * 256 + threadIdx.x;
    if (i < n) g_mask[ids[i]] = 1;
}

// ============================================================================
// masked copy: node_memories -> out for rows not later overwritten
// ============================================================================
__global__ void __launch_bounds__(256) k_copy_masked(const float4* __restrict__ src,
                                                     float4* __restrict__ dst,
                                                     int nf4) {
    int stride = gridDim.x * 256;
    for (int i = blockIdx.x * 256 + threadIdx.x; i < nf4; i += stride) {
        int row = i >> 5;
        if (g_mask[row] == 0) dst[i] = src[i];
    }
}

// ============================================================================
// persistent GEMM + LayerNorm + scatter
// ============================================================================
__global__ void __launch_bounds__(NTHREADS, 1) rhythm_gemm(
    const int*   __restrict__ node_ids,
    const float* __restrict__ messages,
    const float* __restrict__ node_mem,
    const float* __restrict__ conv_w,
    const float* __restrict__ lin_w,
    const float* __restrict__ lin_b,
    const float* __restrict__ ln_g,
    const float* __restrict__ ln_bt,
    float*       __restrict__ out,
    int ntiles, int period, int pad)
{
    extern __shared__ float sX[];                 // [STAGES][TILE_M * SX_STRIDE]
    __shared__ int    s_node[STAGES][TILE_M];
    __shared__ float2 s_part[8][TILE_M];
    __shared__ float2 s_stats[TILE_M];

    const int tid  = threadIdx.x;
    const int lane = tid & 31;
    const int wid  = tid >> 5;

    // ---- static per-warp W' fragments (A operand of C^T = W' * x^T) ----
    const int d1 = wid * 16 + (lane >> 2);
    const int d2 = d1 + 8;
    const int kbase = lane & 3;

    uint32_t areg[32][4];
#pragma unroll
    for (int kt = 0; kt < 32; kt++) {
        int k1 = kt * 8 + kbase, k2 = k1 + 4;
        float w1 = __ldg(conv_w + k1 * period + pad);
        float w2 = __ldg(conv_w + k2 * period + pad);
        areg[kt][0] = f2tf32(__ldg(lin_w + d1 * KDIM + k1) * w1);
        areg[kt][1] = f2tf32(__ldg(lin_w + d2 * KDIM + k1) * w1);
        areg[kt][2] = f2tf32(__ldg(lin_w + d1 * KDIM + k2) * w2);
        areg[kt][3] = f2tf32(__ldg(lin_w + d2 * KDIM + k2) * w2);
    }
    const float bia1 = __ldg(lin_b + d1), bia2 = __ldg(lin_b + d2);
    const float gm1  = __ldg(ln_g + d1),  gm2  = __ldg(ln_g + d2);
    const float bt1  = __ldg(ln_bt + d1), bt2  = __ldg(ln_bt + d2);

    // ---- cp.async stage: 64 rows x 256 floats (64 float4 chunks/row) ----
    auto stage_tile = [&](int tile, int slot) {
        if (tile >= ntiles) return;
        float* dstS = sX + (size_t)slot * TILE_M * SX_STRIDE;
#pragma unroll
        for (int i = 0; i < 16; i++) {
            int idx = i * NTHREADS + tid;     // 4096 chunks of 16B
            int row = idx >> 6, c = idx & 63;
            long long gr = (long long)tile * TILE_M + row;
            const float4* src;
            if (c < 32) {
                src = (const float4*)messages + gr * 32 + c;
            } else {
                int nd = __ldg(node_ids + gr);
                if (c == 32) s_node[slot][row] = nd;
                src = (const float4*)node_mem + (long long)nd * 32 + (c - 32);
            }
            cp_async16(smem_u32(dstS + row * SX_STRIDE + c * 4), src);
        }
    };

    // ---- prologue: prefetch two tiles ----
    stage_tile(blockIdx.x, 0);
    CP_COMMIT();
    stage_tile(blockIdx.x + gridDim.x, 1);
    CP_COMMIT();

    for (int it = 0;; it++) {
        int tile = blockIdx.x + it * gridDim.x;
        if (tile >= ntiles) break;

        CP_WAIT1();
        __syncthreads();
        const int slot = it % STAGES;
        const float* X = sX + (size_t)slot * TILE_M * SX_STRIDE;

        float cacc[8][4];
#pragma unroll
        for (int nt = 0; nt < 8; nt++)
#pragma unroll
            for (int j = 0; j < 4; j++) cacc[nt][j] = 0.f;

        const float* xb = X + (lane >> 2) * SX_STRIDE + kbase;
#pragma unroll
        for (int kt = 0; kt < 32; kt++) {
#pragma unroll
            for (int nt = 0; nt < 8; nt++) {
                const float* xp = xb + nt * 8 * SX_STRIDE + kt * 8;
                uint32_t b0 = f2tf32(xp[0]);
                uint32_t b1 = f2tf32(xp[4]);
                mma_tf32(cacc[nt], areg[kt][0], areg[kt][1],
                         areg[kt][2], areg[kt][3], b0, b1);
            }
        }

        // ---- prefetch tile two iterations ahead into recycled slot ----
        stage_tile(tile + 2 * gridDim.x, (it + 2) % STAGES);
        CP_COMMIT();

        // ---- bias + per-row partial stats (sum over this warp's 16 d) ----
#pragma unroll
        for (int nt = 0; nt < 8; nt++) {
            float vA0 = cacc[nt][0] + bia1;   // (d1, brA)
            float vA1 = cacc[nt][1] + bia1;   // (d1, brA+1)
            float vB0 = cacc[nt][2] + bia2;   // (d2, brA)
            float vB1 = cacc[nt][3] + bia2;   // (d2, brA+1)
            cacc[nt][0] = vA0; cacc[nt][1] = vA1;
            cacc[nt][2] = vB0; cacc[nt][3] = vB1;
            float s0 = vA0 + vB0, q0 = vA0 * vA0 + vB0 * vB0;
            float s1 = vA1 + vB1, q1 = vA1 * vA1 + vB1 * vB1;
#pragma unroll
            for (int m = 4; m <= 16; m <<= 1) {
                s0 += __shfl_xor_sync(0xffffffffu, s0, m);
                q0 += __shfl_xor_sync(0xffffffffu, q0, m);
                s1 += __shfl_xor_sync(0xffffffffu, s1, m);
                q1 += __shfl_xor_sync(0xffffffffu, q1, m);
            }
            if (lane < 4) {
                int brA = nt * 8 + lane * 2;
                s_part[wid][brA]     = make_float2(s0, q0);
                s_part[wid][brA + 1] = make_float2(s1, q1);
            }
        }
        __syncthreads();

        if (tid < TILE_M) {
            float s = 0.f, q = 0.f;
#pragma unroll
            for (int w = 0; w < 8; w++) {
                float2 p = s_part[w][tid];
                s += p.x; q += p.y;
            }
            float mean = s * (1.0f / 128.0f);
            float var  = q * (1.0f / 128.0f) - mean * mean;
            s_stats[tid] = make_float2(mean, rsqrtf(var + 1e-5f));
        }
        __syncthreads();

        // ---- normalize + scatter store ----
#pragma unroll
        for (int nt = 0; nt < 8; nt++) {
            int brA = nt * 8 + (lane & 3) * 2;
            float2 stA = s_stats[brA], stB = s_stats[brA + 1];
            long long ndA = s_node[slot][brA];
            long long ndB = s_node[slot][brA + 1];
            out[ndA * NDIM + d1] = (cacc[nt][0] - stA.x) * stA.y * gm1 + bt1;
            out[ndB * NDIM + d1] = (cacc[nt][1] - stB.x) * stB.y * gm1 + bt1;
            out[ndA * NDIM + d2] = (cacc[nt][2] - stA.x) * stA.y * gm2 + bt2;
            out[ndB * NDIM + d2] = (cacc[nt][3] - stB.x) * stB.y * gm2 + bt2;
        }
    }
    CP_WAIT0();
}

// ============================================================================
// launch
// ============================================================================
extern "C" void kernel_launch(void* const* d_in, const int* in_sizes, int n_in,
                              void* d_out, int out_size) {
    const int*   node_ids = (const int*)  d_in[0];
    const float* messages = (const float*)d_in[1];
    const float* node_mem = (const float*)d_in[2];
    const float* conv_w   = (const float*)d_in[3];
    const float* lin_w    = (const float*)d_in[4];
    const float* lin_b    = (const float*)d_in[5];
    const float* ln_g     = (const float*)d_in[6];
    const float* ln_bt    = (const float*)d_in[7];
    float* out = (float*)d_out;

    int Btot    = in_sizes[1] / NDIM;            // 262144
    int ntiles  = Btot / TILE_M;                 // 4096
    int period  = in_sizes[3] / KDIM;            // 7
    int pad     = period / 2;                    // 3 (L == 1 path)
    int nf4     = out_size / 4;                  // float4 count

    // mask of rows updated by the scatter
    k_clear<<<64, 256>>>((1 << 20) / 16);
    k_mark<<<(Btot + 255) / 256, 256>>>(node_ids, Btot);

    // copy non-updated rows at full occupancy
    k_copy_masked<<<2048, 256>>>((const float4*)node_mem, (float4*)out, nf4);

    // persistent GEMM + LN + scatter
    const int dyn_smem = STAGES * TILE_M * SX_STRIDE * 4;   // ~200 KB
    static int configured = -1;
    if (configured != dyn_smem) {
        cudaFuncSetAttribute(rhythm_gemm, cudaFuncAttributeMaxDynamicSharedMemorySize,
                             dyn_smem);
        configured = dyn_smem;
    }
    rhythm_gemm<<<NCTAS, NTHREADS, dyn_smem>>>(node_ids, messages, node_mem, conv_w,
                                               lin_w, lin_b, ln_g, ln_bt, out,
                                               ntiles, period, pad);
}